// round 11
// baseline (speedup 1.0000x reference)
#include <cuda_runtime.h>
#include <cstdint>

#define WARM_UP 365
#define NPHY    12
#define NMUL    4
#define LENF    15
#define MAX_T   2000
#define MAX_G   4000
#define CHUNK   40
#define GPB     32                 // grid cells per block
#define THREADS (GPB * NMUL)       // 128, thread = (g, m)

// Scratch (allocation-free per harness rules)
__device__ float g_qs[(size_t)MAX_T * MAX_G];   // [t][g], m-averaged
__device__ float g_w[LENF * MAX_G];             // [k][g]
__device__ float g_sink[THREADS];               // write sink for m!=0 lanes

__device__ __forceinline__ float fast_lg2(float x) {
    float r; asm("lg2.approx.f32 %0, %1;" : "=f"(r) : "f"(x)); return r;
}
__device__ __forceinline__ float fast_ex2(float x) {
    float r; asm("ex2.approx.f32 %0, %1;" : "=f"(r) : "f"(x)); return r;
}
__device__ __forceinline__ uint32_t smem_u32(const void* p) {
    return (uint32_t)__cvta_generic_to_shared(p);
}

// ---------------------------------------------------------------------------
// Kernel 1: HBV scan. Thread = (g, m). Double-buffered cp.async forcing.
// q is m-averaged in-warp (2x shfl) and stored branch-free: m!=0 lanes
// write to a sink with stride 0. EXACT=true -> no per-iteration branches.
// ---------------------------------------------------------------------------
template <bool EXACT>
__global__ __launch_bounds__(THREADS)
void hbv_scan_kernel(const float* __restrict__ x_phy,
                     const float* __restrict__ params,
                     int T, int G)
{
    // +1 padding row so the steady-state prefetch of row i+1 never goes OOB
    __shared__ float sbufA[CHUNK + 1][GPB * 3];
    __shared__ float sbufB[CHUNK + 1][GPB * 3];

    const int tidx = threadIdx.x;
    const int gl   = tidx >> 2;
    const int m    = tidx & 3;
    const int g    = blockIdx.x * GPB + gl;
    const bool active = EXACT || (g < G);

    const float lb[NPHY] = {1.0f, 50.0f, 0.05f, 0.01f, 0.001f, 0.2f,
                            0.0f, 0.0f, -2.5f, 0.5f, 0.0f, 0.0f};
    const float ub[NPHY] = {6.0f, 1000.0f, 0.9f, 0.5f, 0.2f, 1.0f,
                            10.0f, 100.0f, 2.5f, 10.0f, 0.1f, 0.2f};

    float phy[NPHY];
#pragma unroll
    for (int i = 0; i < NPHY; i++) phy[i] = 0.5f;
    if (active) {
        const float* pp = params + (size_t)g * (NPHY * NMUL + 2);
#pragma unroll
        for (int i = 0; i < NPHY; i++)
            phy[i] = lb[i] + pp[i * NMUL + m] * (ub[i] - lb[i]);
    }
    const float beta  = phy[0],  fc    = phy[1],  k0  = phy[2];
    const float k1    = phy[3],  k2    = phy[4],  lp  = phy[5];
    const float perc  = phy[6],  uzl   = phy[7],  tt  = phy[8];
    const float cfmax = phy[9],  cfr   = phy[10], cwh = phy[11];

    const float inv_lpfc  = 1.0f / (lp * fc);
    const float cfr_cfmax = cfr * cfmax;
    const float blg_ifc   = beta * fast_lg2(1.0f / fc);   // fold /fc into exp

    float snowpack = 0.001f, meltwater = 0.001f, sm = 0.001f;
    float suz = 0.001f, slz = 0.001f;

    const int row = G * 3;
    const float* gsrc = x_phy + (size_t)blockIdx.x * (GPB * 3);
    const int fbase = gl * 3;

    // branch-free store target: m==0 lanes -> g_qs[t*G+g], else sink (stride 0)
    const bool writer = (m == 0) && active;
    float* qout = writer ? (g_qs + g) : (g_sink + tidx);
    const int qstride = writer ? G : 0;

    auto issue_chunk = [&](float (*sb)[GPB * 3], int t0) {
        const int PK = GPB * 3 / 4;          // 16B packets per row (24)
        const int NV4 = CHUNK * PK;
#pragma unroll 2
        for (int idx = tidx; idx < NV4; idx += THREADS) {
            int i = idx / PK;
            int j = idx - i * PK;
            int t = t0 + i;
            if (!EXACT && t >= T) t = T - 1;
            const float* src = gsrc + (size_t)t * row + j * 4;
            uint32_t dst = smem_u32(&sb[i][j * 4]);
            asm volatile("cp.async.cg.shared.global [%0], [%1], 16;"
                         :: "r"(dst), "l"(src));
        }
        asm volatile("cp.async.commit_group;");
    };

    issue_chunk(sbufA, 0);
    asm volatile("cp.async.wait_group 0;");
    __syncthreads();

    // pipelined forcing-derived terms for the upcoming step (all off-chain)
    float rain, snow, melt_cap, refr_cap, PE, om_pe;
    auto make_terms = [&](const float* f) {
        float P  = f[0];
        float Tt = f[1];
        PE       = f[2];
        rain = (Tt >= tt) ? P : 0.0f;
        snow = P - rain;
        melt_cap = fmaxf(cfmax * (Tt - tt), 0.0f);
        refr_cap = fmaxf(cfr_cfmax * (tt - Tt), 0.0f);
        om_pe = 1.0f - PE * inv_lpfc;
    };
    make_terms(&sbufA[0][fbase]);

    const int nchunks = (T + CHUNK - 1) / CHUNK;
    float (*cur)[GPB * 3] = sbufA;
    float (*nxt)[GPB * 3] = sbufB;

    for (int c = 0; c < nchunks; c++) {
        const int t0 = c * CHUNK;
        const bool has_next = (c + 1 < nchunks);
        if (has_next)
            issue_chunk(nxt, t0 + CHUNK);

#pragma unroll 8
        for (int i = 0; i < CHUNK; i++) {
            // ---- soil wetness: MUFU pair straight off carried sm ----
            float sw = fast_ex2(fmaf(beta, fast_lg2(sm), blg_ifc));
            sw = fminf(sw, 1.0f);
            float oms = 1.0f - sw;

            // ---- snow module (inputs already in registers) ----
            float sp1  = snowpack + snow;
            float melt = fminf(melt_cap, sp1);
            float mw1  = meltwater + melt;
            float sp2  = sp1 - melt;
            float refreeze = fminf(refr_cap, mw1);
            float sp3  = sp2 + refreeze;
            float mw2  = mw1 - refreeze;
            float thr  = cwh * sp3;
            float tosoil = fmaxf(mw2 - thr, 0.0f);
            meltwater  = fminf(mw2, thr);
            snowpack   = sp3;

            // ---- soil module (shortened chain) ----
            float inflow   = rain + tosoil;
            float recharge = inflow * sw;
            float sm2 = fmaf(inflow, oms, sm);
            float sm3 = fminf(sm2, fc);
            float excess = sm2 - sm3;
            sm = fmaxf(fmaxf(sm3 * om_pe, sm3 - PE), 1e-5f);

            // ---- response routing ----
            float suz1 = suz + recharge + excess;
            float suz2 = fmaxf(suz1 - perc, 0.0f);
            float prc  = suz1 - suz2;
            float q0   = k0 * fmaxf(suz2 - uzl, 0.0f);
            float suz3 = suz2 - q0;
            float q1   = k1 * suz3;
            suz = suz3 - q1;
            float slz1 = slz + prc;
            float q2   = k2 * slz1;
            slz = slz1 - q2;

            // ---- prefetch next step's forcing terms (off critical path) ----
            make_terms(&cur[i + 1][fbase]);

            // ---- m-mean via shfl (off carried chain), branch-free store ----
            float q = q0 + q1 + q2;
            q += __shfl_xor_sync(0xffffffffu, q, 1);
            q += __shfl_xor_sync(0xffffffffu, q, 2);
            if (EXACT) {
                *qout = q * 0.25f;
                qout += qstride;
            } else {
                int t = t0 + i;
                if (t < T) {
                    *qout = q * 0.25f;
                    qout += qstride;
                }
            }
        }

        if (has_next) {
            asm volatile("cp.async.wait_group 0;");
            __syncthreads();
            float (*tmp)[GPB * 3] = cur; cur = nxt; nxt = tmp;
            make_terms(&cur[0][fbase]);
        }
    }
}

// ---------------------------------------------------------------------------
// Kernel 2: normalized gamma routing weights (Γ(aa)·th^aa cancels).
// ---------------------------------------------------------------------------
__global__ __launch_bounds__(128)
void hbv_w_kernel(const float* __restrict__ params, int G)
{
    int g = blockIdx.x * blockDim.x + threadIdx.x;
    if (g >= G) return;
    const float* pp = params + (size_t)g * (NPHY * NMUL + 2);
    float a  = pp[NPHY * NMUL + 0] * 2.9f;
    float b  = pp[NPHY * NMUL + 1] * 6.5f;
    float aa = fmaxf(a, 0.0f) + 0.1f;
    float th = fmaxf(b, 0.0f) + 0.5f;
    float inv_th = 1.0f / th;

    float w[LENF];
    float s = 0.0f;
#pragma unroll
    for (int k = 0; k < LENF; k++) {
        float tg = (float)k + 0.5f;
        float v = expf((aa - 1.0f) * logf(tg) - tg * inv_th);
        w[k] = v;
        s += v;
    }
    float inv_s = 1.0f / s;
#pragma unroll
    for (int k = 0; k < LENF; k++)
        g_w[k * MAX_G + g] = w[k] * inv_s;
}

// ---------------------------------------------------------------------------
// Kernel 3: causal 15-tap conv on averaged q; rolling register window.
// ---------------------------------------------------------------------------
#define TS 16
__global__ __launch_bounds__(256)
void hbv_conv_kernel(float* __restrict__ out, int T, int G)
{
    int g = blockIdx.x * blockDim.x + threadIdx.x;
    if (g >= G) return;
    int t0 = WARM_UP + blockIdx.y * TS;

    float w[LENF];
#pragma unroll
    for (int k = 0; k < LENF; k++)
        w[k] = g_w[k * MAX_G + g];

    float qb[LENF - 1];
#pragma unroll
    for (int j = 0; j < LENF - 1; j++)
        qb[j] = g_qs[(size_t)(t0 - (LENF - 1) + j) * G + g];

#pragma unroll
    for (int i = 0; i < TS; i++) {
        int t = t0 + i;
        if (t >= T) break;
        float qt = g_qs[(size_t)t * G + g];
        float acc = qt * w[0];
#pragma unroll
        for (int k = 1; k < LENF; k++)
            acc += qb[LENF - 1 - k] * w[k];
#pragma unroll
        for (int j = 0; j < LENF - 2; j++)
            qb[j] = qb[j + 1];
        qb[LENF - 2] = qt;
        out[(size_t)(t - WARM_UP) * G + g] = acc;
    }
}

// ---------------------------------------------------------------------------
extern "C" void kernel_launch(void* const* d_in, const int* in_sizes, int n_in,
                              void* d_out, int out_size)
{
    int ix = 0, ip = 1;
    if (in_sizes[0] < in_sizes[1]) { ix = 1; ip = 0; }
    const float* x_phy  = (const float*)d_in[ix];
    const float* params = (const float*)d_in[ip];
    float* out = (float*)d_out;

    int G = in_sizes[ip] / (NPHY * NMUL + 2);
    int T = in_sizes[ix] / (3 * G);

    int nblk = (G + GPB - 1) / GPB;
    if ((G % GPB) == 0 && (T % CHUNK) == 0)
        hbv_scan_kernel<true><<<nblk, THREADS>>>(x_phy, params, T, G);
    else
        hbv_scan_kernel<false><<<nblk, THREADS>>>(x_phy, params, T, G);

    hbv_w_kernel<<<(G + 127) / 128, 128>>>(params, G);
    dim3 gconv((G + 255) / 256, (T - WARM_UP + TS - 1) / TS);
    hbv_conv_kernel<<<gconv, 256>>>(out, T, G);
}

// round 12
// speedup vs baseline: 1.8844x; 1.8844x over previous
#include <cuda_runtime.h>
#include <cstdint>

#define WARM_UP 365
#define NPHY    12
#define NMUL    4
#define LENF    15
#define MAX_T   2000
#define MAX_G   4000
#define CHUNK   40
#define GPB     32                 // grid cells per block
#define THREADS (GPB * NMUL)       // 128, thread = (g, m)

// Scratch (allocation-free per harness rules)
__device__ float g_qs4[(size_t)MAX_T * MAX_G * NMUL];  // [t][g*4+m]
__device__ float g_w[LENF * MAX_G];                    // [k][g]

__device__ __forceinline__ float fast_lg2(float x) {
    float r; asm("lg2.approx.f32 %0, %1;" : "=f"(r) : "f"(x)); return r;
}
__device__ __forceinline__ float fast_ex2(float x) {
    float r; asm("ex2.approx.f32 %0, %1;" : "=f"(r) : "f"(x)); return r;
}
__device__ __forceinline__ uint32_t smem_u32(const void* p) {
    return (uint32_t)__cvta_generic_to_shared(p);
}

// ---------------------------------------------------------------------------
// Kernel 1: HBV scan. Thread = (g, m). Double-buffered cp.async forcing.
// EXACT=true: G % GPB == 0 and T % CHUNK == 0 -> no per-iteration branches.
// ---------------------------------------------------------------------------
template <bool EXACT>
__global__ __launch_bounds__(THREADS)
void hbv_scan_kernel(const float* __restrict__ x_phy,
                     const float* __restrict__ params,
                     int T, int G)
{
    // +1 padding row so the steady-state prefetch of row i+1 never goes OOB
    __shared__ float sbufA[CHUNK + 1][GPB * 3];
    __shared__ float sbufB[CHUNK + 1][GPB * 3];

    const int tidx = threadIdx.x;
    const int gl   = tidx >> 2;
    const int m    = tidx & 3;
    const int g    = blockIdx.x * GPB + gl;
    const bool active = EXACT || (g < G);

    const float lb[NPHY] = {1.0f, 50.0f, 0.05f, 0.01f, 0.001f, 0.2f,
                            0.0f, 0.0f, -2.5f, 0.5f, 0.0f, 0.0f};
    const float ub[NPHY] = {6.0f, 1000.0f, 0.9f, 0.5f, 0.2f, 1.0f,
                            10.0f, 100.0f, 2.5f, 10.0f, 0.1f, 0.2f};

    float phy[NPHY];
#pragma unroll
    for (int i = 0; i < NPHY; i++) phy[i] = 0.5f;
    if (active) {
        const float* pp = params + (size_t)g * (NPHY * NMUL + 2);
#pragma unroll
        for (int i = 0; i < NPHY; i++)
            phy[i] = lb[i] + pp[i * NMUL + m] * (ub[i] - lb[i]);
    }
    const float beta  = phy[0],  fc    = phy[1],  k0  = phy[2];
    const float k1    = phy[3],  k2    = phy[4],  lp  = phy[5];
    const float perc  = phy[6],  uzl   = phy[7],  tt  = phy[8];
    const float cfmax = phy[9],  cfr   = phy[10], cwh = phy[11];

    const float inv_lpfc  = 1.0f / (lp * fc);
    const float cfr_cfmax = cfr * cfmax;
    const float blg_ifc   = beta * fast_lg2(1.0f / fc);  // fold /fc into exp
    const float onek0     = 1.0f - k0;
    const float k0uzl     = k0 * uzl;
    const float c1        = 1.0f - k1;
    const float c2        = 1.0f - k2;

    float snowpack = 0.001f, meltwater = 0.001f, sm = 0.001f;
    float suz = 0.001f, slz = 0.001f;

    const int row = G * 3;
    const float* gsrc = x_phy + (size_t)blockIdx.x * (GPB * 3);
    const int fbase = gl * 3;
    const int strideQ = G * NMUL;
    float* qout = g_qs4 + ((g << 2) | m);   // induction pointer

    auto issue_chunk = [&](float (*sb)[GPB * 3], int t0) {
        const int PK = GPB * 3 / 4;          // 16B packets per row (24)
        const int NV4 = CHUNK * PK;
#pragma unroll 2
        for (int idx = tidx; idx < NV4; idx += THREADS) {
            int i = idx / PK;
            int j = idx - i * PK;
            int t = t0 + i;
            if (!EXACT && t >= T) t = T - 1;
            const float* src = gsrc + (size_t)t * row + j * 4;
            uint32_t dst = smem_u32(&sb[i][j * 4]);
            asm volatile("cp.async.cg.shared.global [%0], [%1], 16;"
                         :: "r"(dst), "l"(src));
        }
        asm volatile("cp.async.commit_group;");
    };

    issue_chunk(sbufA, 0);
    asm volatile("cp.async.wait_group 0;");
    __syncthreads();

    // pipelined forcing-derived terms for the upcoming step (all off-chain)
    float rain, snow, melt_cap, refr_cap, PE, om_pe;
    auto make_terms = [&](const float* f) {
        float P  = f[0];
        float Tt = f[1];
        PE       = f[2];
        float d  = Tt - tt;
        rain = (d >= 0.0f) ? P : 0.0f;
        snow = P - rain;
        melt_cap = fmaxf(cfmax * d, 0.0f);
        refr_cap = fmaxf(-cfr_cfmax * d, 0.0f);
        om_pe = 1.0f - PE * inv_lpfc;
    };
    make_terms(&sbufA[0][fbase]);

    const int nchunks = (T + CHUNK - 1) / CHUNK;
    float (*cur)[GPB * 3] = sbufA;
    float (*nxt)[GPB * 3] = sbufB;

    for (int c = 0; c < nchunks; c++) {
        const int t0 = c * CHUNK;
        const bool has_next = (c + 1 < nchunks);
        if (has_next)
            issue_chunk(nxt, t0 + CHUNK);

#pragma unroll 8
        for (int i = 0; i < CHUNK; i++) {
            // ---- soil wetness: MUFU pair straight off carried sm.
            // Invariant sm <= fc  =>  sw <= 1, no clamp needed.
            float sw = fast_ex2(fmaf(beta, fast_lg2(sm), blg_ifc));

            // ---- snow module: melt/refreeze merged into one transfer
            // (at most one of melt_cap/refr_cap is nonzero).
            float sp1 = snowpack + snow;
            float a   = fminf(melt_cap, sp1);        // melt
            float b   = fminf(refr_cap, meltwater);  // refreeze
            float transfer = a - b;
            float sp3 = sp1 - transfer;
            float mw2 = meltwater + transfer;
            float thr = cwh * sp3;
            float tosoil = fmaxf(mw2 - thr, 0.0f);
            meltwater = fminf(mw2, thr);
            snowpack  = sp3;

            // ---- soil module ----
            float inflow   = rain + tosoil;
            float sminf    = sm + inflow;            // parallel to MUFU chain
            float recharge = inflow * sw;
            float sm2 = sminf - recharge;
            float sm3 = fminf(sm2, fc);
            float excess = sm2 - sm3;
            sm = fmaxf(fmaxf(sm3 * om_pe, sm3 - PE), 1e-5f);

            // ---- response routing (q assembled off-chain) ----
            float suz1 = suz + recharge + excess;
            float suz2 = fmaxf(suz1 - perc, 0.0f);
            float suz3 = fminf(suz2, fmaf(onek0, suz2, k0uzl));
            float suzn = c1 * suz3;
            float prc  = suz1 - suz2;
            float slz1 = slz + prc;
            float q2   = k2 * slz1;
            float q01  = suz2 - suzn;                // == q0 + q1
            suz = suzn;
            slz = c2 * slz1;

            // ---- prefetch next step's forcing terms (off critical path) ----
            make_terms(&cur[i + 1][fbase]);

            // ---- unconditional coalesced store (no branch in EXACT path) ----
            float q = q01 + q2;
            if (EXACT) {
                *qout = q;
                qout += strideQ;
            } else {
                int t = t0 + i;
                if (active && t < T)
                    qout[(size_t)(t - t0) * strideQ] = q;
            }
        }
        if (!EXACT)
            qout += (size_t)CHUNK * strideQ;

        if (has_next) {
            asm volatile("cp.async.wait_group 0;");
            __syncthreads();
            float (*tmp)[GPB * 3] = cur; cur = nxt; nxt = tmp;
            make_terms(&cur[0][fbase]);
        }
    }
}

// ---------------------------------------------------------------------------
// Kernel 2: normalized gamma routing weights (Γ(aa)·th^aa cancels).
// ---------------------------------------------------------------------------
__global__ __launch_bounds__(128)
void hbv_w_kernel(const float* __restrict__ params, int G)
{
    int g = blockIdx.x * blockDim.x + threadIdx.x;
    if (g >= G) return;
    const float* pp = params + (size_t)g * (NPHY * NMUL + 2);
    float a  = pp[NPHY * NMUL + 0] * 2.9f;
    float b  = pp[NPHY * NMUL + 1] * 6.5f;
    float aa = fmaxf(a, 0.0f) + 0.1f;
    float th = fmaxf(b, 0.0f) + 0.5f;
    float inv_th = 1.0f / th;

    float w[LENF];
    float s = 0.0f;
#pragma unroll
    for (int k = 0; k < LENF; k++) {
        float tg = (float)k + 0.5f;
        float v = expf((aa - 1.0f) * logf(tg) - tg * inv_th);
        w[k] = v;
        s += v;
    }
    float inv_s = 1.0f / s;
#pragma unroll
    for (int k = 0; k < LENF; k++)
        g_w[k * MAX_G + g] = w[k] * inv_s;
}

// ---------------------------------------------------------------------------
// Kernel 3: mean over NMUL (float4) + causal 15-tap conv; rolling window.
// TS=64 cuts the history re-read amplification to (64+14)/64 = 1.22x.
// ---------------------------------------------------------------------------
#define TS 64
__global__ __launch_bounds__(256)
void hbv_conv_kernel(float* __restrict__ out, int T, int G)
{
    int g = blockIdx.x * blockDim.x + threadIdx.x;
    if (g >= G) return;
    int t0 = WARM_UP + blockIdx.y * TS;

    const float4* q4 = (const float4*)g_qs4;   // index t*G + g

    float w[LENF];
#pragma unroll
    for (int k = 0; k < LENF; k++)
        w[k] = g_w[k * MAX_G + g];

    float qb[LENF - 1];
#pragma unroll
    for (int j = 0; j < LENF - 1; j++) {
        float4 v = q4[(size_t)(t0 - (LENF - 1) + j) * G + g];
        qb[j] = 0.25f * (v.x + v.y + v.z + v.w);
    }

#pragma unroll
    for (int i = 0; i < TS; i++) {
        int t = t0 + i;
        if (t >= T) break;
        float4 v = q4[(size_t)t * G + g];
        float qt = 0.25f * (v.x + v.y + v.z + v.w);
        float acc = qt * w[0];
#pragma unroll
        for (int k = 1; k < LENF; k++)
            acc += qb[LENF - 1 - k] * w[k];
#pragma unroll
        for (int j = 0; j < LENF - 2; j++)
            qb[j] = qb[j + 1];
        qb[LENF - 2] = qt;
        out[(size_t)(t - WARM_UP) * G + g] = acc;
    }
}

// ---------------------------------------------------------------------------
extern "C" void kernel_launch(void* const* d_in, const int* in_sizes, int n_in,
                              void* d_out, int out_size)
{
    int ix = 0, ip = 1;
    if (in_sizes[0] < in_sizes[1]) { ix = 1; ip = 0; }
    const float* x_phy  = (const float*)d_in[ix];
    const float* params = (const float*)d_in[ip];
    float* out = (float*)d_out;

    int G = in_sizes[ip] / (NPHY * NMUL + 2);
    int T = in_sizes[ix] / (3 * G);

    int nblk = (G + GPB - 1) / GPB;
    if ((G % GPB) == 0 && (T % CHUNK) == 0)
        hbv_scan_kernel<true><<<nblk, THREADS>>>(x_phy, params, T, G);
    else
        hbv_scan_kernel<false><<<nblk, THREADS>>>(x_phy, params, T, G);

    hbv_w_kernel<<<(G + 127) / 128, 128>>>(params, G);
    dim3 gconv((G + 255) / 256, (T - WARM_UP + TS - 1) / TS);
    hbv_conv_kernel<<<gconv, 256>>>(out, T, G);
}

// round 14
// speedup vs baseline: 2.1034x; 1.1162x over previous
#include <cuda_runtime.h>
#include <cstdint>

#define WARM_UP 365
#define NPHY    12
#define NMUL    4
#define LENF    15
#define MAX_T   2000
#define MAX_G   4000
#define CHUNK   40
#define GPB     32                 // grid cells per block
#define THREADS (GPB * NMUL)       // 128, thread = (g, m)

// dynamic smem layout (floats):
//   sbufA[(CHUNK+1)][GPB*3], sbufB[(CHUNK+1)][GPB*3], qsm[CHUNK][THREADS]
#define SBUF_FLOATS ((CHUNK + 1) * GPB * 3)
#define SMEM_FLOATS (2 * SBUF_FLOATS + CHUNK * THREADS)
#define SMEM_BYTES  (SMEM_FLOATS * 4)

// Scratch (allocation-free per harness rules)
__device__ float g_qs[(size_t)MAX_T * MAX_G];   // [t][g], m-averaged
__device__ float g_w[LENF * MAX_G];             // [k][g]

__device__ __forceinline__ float fast_lg2(float x) {
    float r; asm("lg2.approx.f32 %0, %1;" : "=f"(r) : "f"(x)); return r;
}
__device__ __forceinline__ float fast_ex2(float x) {
    float r; asm("ex2.approx.f32 %0, %1;" : "=f"(r) : "f"(x)); return r;
}
__device__ __forceinline__ uint32_t smem_u32(const void* p) {
    return (uint32_t)__cvta_generic_to_shared(p);
}

// ---------------------------------------------------------------------------
// Kernel 1: HBV scan. Thread = (g, m). Double-buffered cp.async forcing.
// q goes to smem per step (STS, no convergence cost); once per chunk a
// cooperative pass averages the 4 m-values and writes g_qs coalesced.
// EXACT=true: G % GPB == 0 and T % CHUNK == 0 -> no per-iteration branches.
// ---------------------------------------------------------------------------
template <bool EXACT>
__global__ __launch_bounds__(THREADS)
void hbv_scan_kernel(const float* __restrict__ x_phy,
                     const float* __restrict__ params,
                     int T, int G)
{
    extern __shared__ float dynsm[];
    float (*sbufA)[GPB * 3] = (float (*)[GPB * 3])dynsm;
    float (*sbufB)[GPB * 3] = (float (*)[GPB * 3])(dynsm + SBUF_FLOATS);
    float (*qsm)[THREADS]   = (float (*)[THREADS])(dynsm + 2 * SBUF_FLOATS);

    const int tidx = threadIdx.x;
    const int gl   = tidx >> 2;
    const int m    = tidx & 3;
    const int g    = blockIdx.x * GPB + gl;
    const int g0   = blockIdx.x * GPB;
    const bool active = EXACT || (g < G);

    const float lb[NPHY] = {1.0f, 50.0f, 0.05f, 0.01f, 0.001f, 0.2f,
                            0.0f, 0.0f, -2.5f, 0.5f, 0.0f, 0.0f};
    const float ub[NPHY] = {6.0f, 1000.0f, 0.9f, 0.5f, 0.2f, 1.0f,
                            10.0f, 100.0f, 2.5f, 10.0f, 0.1f, 0.2f};

    float phy[NPHY];
#pragma unroll
    for (int i = 0; i < NPHY; i++) phy[i] = 0.5f;
    if (active) {
        const float* pp = params + (size_t)g * (NPHY * NMUL + 2);
#pragma unroll
        for (int i = 0; i < NPHY; i++)
            phy[i] = lb[i] + pp[i * NMUL + m] * (ub[i] - lb[i]);
    }
    const float beta  = phy[0],  fc    = phy[1],  k0  = phy[2];
    const float k1    = phy[3],  k2    = phy[4],  lp  = phy[5];
    const float perc  = phy[6],  uzl   = phy[7],  tt  = phy[8];
    const float cfmax = phy[9],  cfr   = phy[10], cwh = phy[11];

    const float inv_lpfc  = 1.0f / (lp * fc);
    const float cfr_cfmax = cfr * cfmax;
    const float blg_ifc   = beta * fast_lg2(1.0f / fc);  // fold /fc into exp
    const float onek0     = 1.0f - k0;
    const float k0uzl     = k0 * uzl;
    const float c1        = 1.0f - k1;
    const float c2        = 1.0f - k2;

    float snowpack = 0.001f, meltwater = 0.001f, sm = 0.001f;
    float suz = 0.001f, slz = 0.001f;

    const int row = G * 3;
    const float* gsrc = x_phy + (size_t)blockIdx.x * (GPB * 3);
    const int fbase = gl * 3;

    auto issue_chunk = [&](float (*sb)[GPB * 3], int t0) {
        const int PK = GPB * 3 / 4;          // 16B packets per row (24)
        const int NV4 = CHUNK * PK;
#pragma unroll 2
        for (int idx = tidx; idx < NV4; idx += THREADS) {
            int i = idx / PK;
            int j = idx - i * PK;
            int t = t0 + i;
            if (!EXACT && t >= T) t = T - 1;
            const float* src = gsrc + (size_t)t * row + j * 4;
            uint32_t dst = smem_u32(&sb[i][j * 4]);
            asm volatile("cp.async.cg.shared.global [%0], [%1], 16;"
                         :: "r"(dst), "l"(src));
        }
        asm volatile("cp.async.commit_group;");
    };

    issue_chunk(sbufA, 0);
    asm volatile("cp.async.wait_group 0;");
    __syncthreads();

    // pipelined forcing-derived terms for the upcoming step (all off-chain)
    float rain, snow, melt_cap, refr_cap, PE, om_pe;
    auto make_terms = [&](const float* f) {
        float P  = f[0];
        float Tt = f[1];
        PE       = f[2];
        float d  = Tt - tt;
        rain = (d >= 0.0f) ? P : 0.0f;
        snow = P - rain;
        melt_cap = fmaxf(cfmax * d, 0.0f);
        refr_cap = fmaxf(-cfr_cfmax * d, 0.0f);
        om_pe = 1.0f - PE * inv_lpfc;
    };
    make_terms(&sbufA[0][fbase]);

    const int nchunks = (T + CHUNK - 1) / CHUNK;
    float (*cur)[GPB * 3] = sbufA;
    float (*nxt)[GPB * 3] = sbufB;

    for (int c = 0; c < nchunks; c++) {
        const int t0 = c * CHUNK;
        const bool has_next = (c + 1 < nchunks);
        if (has_next)
            issue_chunk(nxt, t0 + CHUNK);

#pragma unroll 8
        for (int i = 0; i < CHUNK; i++) {
            // ---- soil wetness: MUFU pair straight off carried sm.
            // Invariant sm <= fc  =>  sw <= 1, no clamp needed.
            float sw = fast_ex2(fmaf(beta, fast_lg2(sm), blg_ifc));

            // ---- snow module: melt/refreeze merged into one transfer ----
            float sp1 = snowpack + snow;
            float a   = fminf(melt_cap, sp1);        // melt
            float b   = fminf(refr_cap, meltwater);  // refreeze
            float transfer = a - b;
            float sp3 = sp1 - transfer;
            float mw2 = meltwater + transfer;
            float thr = cwh * sp3;
            float tosoil = fmaxf(mw2 - thr, 0.0f);
            meltwater = fminf(mw2, thr);
            snowpack  = sp3;

            // ---- soil module ----
            float inflow   = rain + tosoil;
            float sminf    = sm + inflow;            // parallel to MUFU chain
            float recharge = inflow * sw;
            float sm2 = sminf - recharge;
            float sm3 = fminf(sm2, fc);
            float excess = sm2 - sm3;
            sm = fmaxf(fmaxf(sm3 * om_pe, sm3 - PE), 1e-5f);

            // ---- response routing (q assembled off-chain) ----
            float suz1 = suz + recharge + excess;
            float suz2 = fmaxf(suz1 - perc, 0.0f);
            float suz3 = fminf(suz2, fmaf(onek0, suz2, k0uzl));
            float suzn = c1 * suz3;
            float prc  = suz1 - suz2;
            float slz1 = slz + prc;
            float q2   = k2 * slz1;
            float q01  = suz2 - suzn;                // == q0 + q1
            suz = suzn;
            slz = c2 * slz1;

            // ---- prefetch next step's forcing terms (off critical path) ----
            make_terms(&cur[i + 1][fbase]);

            // ---- store q to smem scratch (issue-only, no convergence) ----
            qsm[i][tidx] = q01 + q2;
        }

        // ---- chunk-level m-average + coalesced write of g_qs ----
        __syncthreads();                 // qsm complete; cur reads done
#pragma unroll
        for (int k = 0; k < (CHUNK * GPB) / THREADS; k++) {   // 10 outputs
            int idx = tidx + k * THREADS;
            int ii  = idx >> 5;          // step within chunk
            int gp  = idx & 31;          // local g
            float4 v = *(const float4*)&qsm[ii][gp << 2];
            float qa = 0.25f * ((v.x + v.y) + (v.z + v.w));
            if (EXACT) {
                g_qs[(size_t)(t0 + ii) * G + g0 + gp] = qa;
            } else {
                if (g0 + gp < G && t0 + ii < T)
                    g_qs[(size_t)(t0 + ii) * G + g0 + gp] = qa;
            }
        }

        if (has_next) {
            asm volatile("cp.async.wait_group 0;");
            __syncthreads();             // all copies landed; qsm reads done
            float (*tmp)[GPB * 3] = cur; cur = nxt; nxt = tmp;
            make_terms(&cur[0][fbase]);
        }
    }
}

// ---------------------------------------------------------------------------
// Kernel 2: normalized gamma routing weights (Γ(aa)·th^aa cancels).
// ---------------------------------------------------------------------------
__global__ __launch_bounds__(128)
void hbv_w_kernel(const float* __restrict__ params, int G)
{
    int g = blockIdx.x * blockDim.x + threadIdx.x;
    if (g >= G) return;
    const float* pp = params + (size_t)g * (NPHY * NMUL + 2);
    float a  = pp[NPHY * NMUL + 0] * 2.9f;
    float b  = pp[NPHY * NMUL + 1] * 6.5f;
    float aa = fmaxf(a, 0.0f) + 0.1f;
    float th = fmaxf(b, 0.0f) + 0.5f;
    float inv_th = 1.0f / th;

    float w[LENF];
    float s = 0.0f;
#pragma unroll
    for (int k = 0; k < LENF; k++) {
        float tg = (float)k + 0.5f;
        float v = expf((aa - 1.0f) * logf(tg) - tg * inv_th);
        w[k] = v;
        s += v;
    }
    float inv_s = 1.0f / s;
#pragma unroll
    for (int k = 0; k < LENF; k++)
        g_w[k * MAX_G + g] = w[k] * inv_s;
}

// ---------------------------------------------------------------------------
// Kernel 3: causal 15-tap conv on averaged q; rolling register window.
// ---------------------------------------------------------------------------
#define TS 32
__global__ __launch_bounds__(256)
void hbv_conv_kernel(float* __restrict__ out, int T, int G)
{
    int g = blockIdx.x * blockDim.x + threadIdx.x;
    if (g >= G) return;
    int t0 = WARM_UP + blockIdx.y * TS;

    float w[LENF];
#pragma unroll
    for (int k = 0; k < LENF; k++)
        w[k] = g_w[k * MAX_G + g];

    float qb[LENF - 1];
#pragma unroll
    for (int j = 0; j < LENF - 1; j++)
        qb[j] = g_qs[(size_t)(t0 - (LENF - 1) + j) * G + g];

#pragma unroll 4
    for (int i = 0; i < TS; i++) {
        int t = t0 + i;
        if (t >= T) break;
        float qt = g_qs[(size_t)t * G + g];
        float acc = qt * w[0];
#pragma unroll
        for (int k = 1; k < LENF; k++)
            acc += qb[LENF - 1 - k] * w[k];
#pragma unroll
        for (int j = 0; j < LENF - 2; j++)
            qb[j] = qb[j + 1];
        qb[LENF - 2] = qt;
        out[(size_t)(t - WARM_UP) * G + g] = acc;
    }
}

// ---------------------------------------------------------------------------
extern "C" void kernel_launch(void* const* d_in, const int* in_sizes, int n_in,
                              void* d_out, int out_size)
{
    int ix = 0, ip = 1;
    if (in_sizes[0] < in_sizes[1]) { ix = 1; ip = 0; }
    const float* x_phy  = (const float*)d_in[ix];
    const float* params = (const float*)d_in[ip];
    float* out = (float*)d_out;

    int G = in_sizes[ip] / (NPHY * NMUL + 2);
    int T = in_sizes[ix] / (3 * G);

    // idempotent attribute set (not an allocation; capture-safe host call)
    cudaFuncSetAttribute(hbv_scan_kernel<true>,
                         cudaFuncAttributeMaxDynamicSharedMemorySize, SMEM_BYTES);
    cudaFuncSetAttribute(hbv_scan_kernel<false>,
                         cudaFuncAttributeMaxDynamicSharedMemorySize, SMEM_BYTES);

    int nblk = (G + GPB - 1) / GPB;
    if ((G % GPB) == 0 && (T % CHUNK) == 0)
        hbv_scan_kernel<true><<<nblk, THREADS, SMEM_BYTES>>>(x_phy, params, T, G);
    else
        hbv_scan_kernel<false><<<nblk, THREADS, SMEM_BYTES>>>(x_phy, params, T, G);

    hbv_w_kernel<<<(G + 127) / 128, 128>>>(params, G);
    dim3 gconv((G + 255) / 256, (T - WARM_UP + TS - 1) / TS);
    hbv_conv_kernel<<<gconv, 256>>>(out, T, G);
}